// round 16
// baseline (speedup 1.0000x reference)
#include <cuda_runtime.h>
#include <cuda_fp16.h>
#include <math.h>
#include <mma.h>

using namespace nvcuda;

#define NN    50000
#define EE    400000
#define HH    128
#define NRBFN 20
#define NOUT  384          // 3*H
#define FCUT  8.0f
#define NT    4096         // distance table resolution

#define NROWPAD 50048      // NN rounded up to 64
#define NTILES  782        // NROWPAD / 64
#define LDH     136        // padded half row (128+8): <=2-way bank conflicts
#define LDF     132        // padded float row

// Scratch (device globals: allocation-free rule)
__device__ __align__(16) half g_spn[NROWPAD * NOUT]; // fp16 sp+b2, 38.4 MB
__device__ __align__(16) half g_vh[NN * NOUT];       // fp16 copy of v, 38.4 MB
__device__ float g_tab[NT * NOUT];                   // fp32 W(d) table, 6.3 MB (L2)

__device__ __forceinline__ float silu_f(float x) {
    return x / (1.0f + __expf(-x));
}

__device__ __forceinline__ void red_add_v4(float* p, float a, float b, float c, float d) {
    asm volatile("red.global.add.v4.f32 [%0], {%1,%2,%3,%4};"
                 :: "l"(p), "f"(a), "f"(b), "f"(c), "f"(d) : "memory");
}

// ---------------------------------------------------------------------------
// Kernel 0: out_s = s ; out_v = v ; g_vh = fp16(v)
// (edge kernel then red-adds messages directly onto out_s / out_v)
// ---------------------------------------------------------------------------
__global__ void init_kernel(const float* __restrict__ s,
                            const float* __restrict__ v,
                            float* __restrict__ out) {
    int i = blockIdx.x * blockDim.x + threadIdx.x;       // float4 index
    const int nS4 = NN * HH / 4;          // 1.6M  : out_s = s
    const int nV4 = NN * NOUT / 4;        // 4.8M  : out_v = v, g_vh = half(v)
    if (i < nS4) {
        ((float4*)out)[i] = ((const float4*)s)[i];
    } else if (i < nS4 + nV4) {
        int j = i - nS4;
        float4 x = ((const float4*)v)[j];
        ((float4*)(out + (size_t)NN * HH))[j] = x;
        half2 h0 = __floats2half2_rn(x.x, x.y);
        half2 h1 = __floats2half2_rn(x.z, x.w);
        unsigned u0 = *reinterpret_cast<unsigned*>(&h0);
        unsigned u1 = *reinterpret_cast<unsigned*>(&h1);
        ((uint2*)g_vh)[j] = make_uint2(u0, u1);
    }
}

// ---------------------------------------------------------------------------
// W(d) table (fp32). 8 rows per block, 128 threads. float4 W2 reads.
// ---------------------------------------------------------------------------
__global__ void build_tab_kernel(const float* __restrict__ rbf_c,
                                 const float* __restrict__ rbf_w,
                                 const float* __restrict__ w1,   // [128,20]
                                 const float* __restrict__ b1,   // [128]
                                 const float* __restrict__ w2,   // [384,128]
                                 const float* __restrict__ b2) { // [384]
    __shared__ float feat_sm[8][NRBFN];
    __shared__ float g_sm[8][HH];
    const int tid  = threadIdx.x;        // 128
    const int row0 = blockIdx.x * 8;

    for (int idx = tid; idx < 8 * NRBFN; idx += 128) {
        int r = idx / NRBFN, i = idx % NRBFN;
        float d   = (row0 + r) * (FCUT / (float)(NT - 1));
        float x   = d / FCUT;
        float env = (x < 1.0f) ? 0.5f * (__cosf(3.14159265358979f * x) + 1.0f) : 0.0f;
        float df  = d - rbf_c[i];
        feat_sm[r][i] = __expf(-fabsf(rbf_w[i]) * df * df) * env;
    }
    __syncthreads();

    float wrow[NRBFN];
    #pragma unroll
    for (int i = 0; i < NRBFN; i++) wrow[i] = w1[tid * NRBFN + i];
    float bb = b1[tid];
    #pragma unroll
    for (int r = 0; r < 8; r++) {
        float a = bb;
        #pragma unroll
        for (int i = 0; i < NRBFN; i++) a += feat_sm[r][i] * wrow[i];
        g_sm[r][tid] = silu_f(a);
    }
    __syncthreads();

    float a0[8], a1[8], a2[8];
    #pragma unroll
    for (int r = 0; r < 8; r++) { a0[r] = 0.f; a1[r] = 0.f; a2[r] = 0.f; }
    const float4* w2r0 = (const float4*)(w2 + (tid)       * HH);
    const float4* w2r1 = (const float4*)(w2 + (tid + 128) * HH);
    const float4* w2r2 = (const float4*)(w2 + (tid + 256) * HH);
    for (int k4 = 0; k4 < HH / 4; k4++) {
        float4 x0 = w2r0[k4], x1 = w2r1[k4], x2 = w2r2[k4];
        #pragma unroll
        for (int r = 0; r < 8; r++) {
            const float* gr = &g_sm[r][k4 * 4];
            float h0 = gr[0], h1 = gr[1], h2 = gr[2], h3 = gr[3];
            a0[r] += h0 * x0.x + h1 * x0.y + h2 * x0.z + h3 * x0.w;
            a1[r] += h0 * x1.x + h1 * x1.y + h2 * x1.z + h3 * x1.w;
            a2[r] += h0 * x2.x + h1 * x2.y + h2 * x2.z + h3 * x2.w;
        }
    }
    float c0 = b2[tid], c1 = b2[tid + 128], c2 = b2[tid + 256];
    #pragma unroll
    for (int r = 0; r < 8; r++) {
        float* o = g_tab + (size_t)(row0 + r) * NOUT;
        o[tid]       = a0[r] + c0;
        o[tid + 128] = a1[r] + c1;
        o[tid + 256] = a2[r] + c2;
    }
}

// ---------------------------------------------------------------------------
// Node scalar MLP: persistent fp16 WMMA GEMM, fp16 output with b2 folded in.
// grid=148, 512 threads (16 warps). Weights staged ONCE in padded smem.
// Register blocking: each warp computes 2 n-tiles per m-tile, sharing one
// A-fragment load per k-step (both layers).
// smem: w1_h[128][136] | w2_h[384][136] | s_h[64][136] | h_h[64][136] | acc[64][132]
// ---------------------------------------------------------------------------
#define MLP_SMEM_BYTES (128*LDH*2 + 384*LDH*2 + 64*LDH*2 + 64*LDH*2 + 64*LDF*4)

__global__ void __launch_bounds__(512, 1)
node_mlp_fp16(const float* __restrict__ s,
              const float* __restrict__ w1,   // [128,128]
              const float* __restrict__ b1,
              const float* __restrict__ w2,   // [384,128]
              const float* __restrict__ b2) { // [384]
    extern __shared__ char smx[];
    half*  w1_h = (half*)smx;                    // 128*136
    half*  w2_h = w1_h + 128 * LDH;              // 384*136
    half*  s_h  = w2_h + 384 * LDH;              // 64*136
    half*  h_h  = s_h  + 64 * LDH;               // 64*136
    float* acc  = (float*)(h_h + 64 * LDH);      // 64*132

    const int tid  = threadIdx.x;                // 512
    const int warp = tid >> 5;                   // 16 warps
    const int mt   = warp >> 2;                  // m-tile 0..3
    const int p    = warp & 3;                   // n-pair 0..3 (tiles 2p, 2p+1)

    // ---- stage weights once ----
    for (int q = tid; q < 128 * 32; q += 512) {
        int r = q >> 5, c4 = q & 31;
        float4 x = ((const float4*)w1)[q];
        half2* d = (half2*)(w1_h + r * LDH + c4 * 4);
        d[0] = __floats2half2_rn(x.x, x.y);
        d[1] = __floats2half2_rn(x.z, x.w);
    }
    for (int q = tid; q < 384 * 32; q += 512) {
        int r = q >> 5, c4 = q & 31;
        float4 x = ((const float4*)w2)[q];
        half2* d = (half2*)(w2_h + r * LDH + c4 * 4);
        d[0] = __floats2half2_rn(x.x, x.y);
        d[1] = __floats2half2_rn(x.z, x.w);
    }
    __syncthreads();

    for (int t = blockIdx.x; t < NTILES; t += gridDim.x) {
        const int n0 = t * 64;

        // load s tile -> half, padded (clamp OOB rows)
        for (int q = tid; q < 64 * 32; q += 512) {
            int r  = q >> 5, c4 = q & 31;
            int gr = n0 + r; if (gr >= NN) gr = NN - 1;
            float4 x = ((const float4*)s)[gr * 32 + c4];
            half2* d = (half2*)(s_h + r * LDH + c4 * 4);
            d[0] = __floats2half2_rn(x.x, x.y);
            d[1] = __floats2half2_rn(x.z, x.w);
        }
        __syncthreads();

        // ---- layer 1: acc = s @ W1^T  (4m x 8n tiles; warp = mt x {2p,2p+1}) ----
        {
            wmma::fragment<wmma::accumulator, 16, 16, 16, float> c0, c1;
            wmma::fill_fragment(c0, 0.0f);
            wmma::fill_fragment(c1, 0.0f);
            for (int k = 0; k < HH; k += 16) {
                wmma::fragment<wmma::matrix_a, 16, 16, 16, half, wmma::row_major> a;
                wmma::load_matrix_sync(a, s_h + mt * 16 * LDH + k, LDH);
                wmma::fragment<wmma::matrix_b, 16, 16, 16, half, wmma::col_major> b;
                wmma::load_matrix_sync(b, w1_h + (p * 32) * LDH + k, LDH);
                wmma::mma_sync(c0, a, b, c0);
                wmma::load_matrix_sync(b, w1_h + (p * 32 + 16) * LDH + k, LDH);
                wmma::mma_sync(c1, a, b, c1);
            }
            wmma::store_matrix_sync(acc + mt * 16 * LDF + p * 32,      c0, LDF,
                                    wmma::mem_row_major);
            wmma::store_matrix_sync(acc + mt * 16 * LDF + p * 32 + 16, c1, LDF,
                                    wmma::mem_row_major);
        }
        __syncthreads();

        // bias + silu -> h_h
        for (int i = tid; i < 64 * 128; i += 512) {
            int r = i >> 7, k = i & 127;
            h_h[r * LDH + k] = __float2half(silu_f(acc[r * LDF + k] + b1[k]));
        }
        __syncthreads();

        // ---- layer 2: 3 chunks of 128 cols; same 2-tile blocking ----
        #pragma unroll 1
        for (int ch = 0; ch < 3; ch++) {
            {
                wmma::fragment<wmma::accumulator, 16, 16, 16, float> c0, c1;
                wmma::fill_fragment(c0, 0.0f);
                wmma::fill_fragment(c1, 0.0f);
                for (int k = 0; k < HH; k += 16) {
                    wmma::fragment<wmma::matrix_a, 16, 16, 16, half, wmma::row_major> a;
                    wmma::load_matrix_sync(a, h_h + mt * 16 * LDH + k, LDH);
                    wmma::fragment<wmma::matrix_b, 16, 16, 16, half, wmma::col_major> b;
                    wmma::load_matrix_sync(b, w2_h + (ch * 128 + p * 32) * LDH + k, LDH);
                    wmma::mma_sync(c0, a, b, c0);
                    wmma::load_matrix_sync(b, w2_h + (ch * 128 + p * 32 + 16) * LDH + k, LDH);
                    wmma::mma_sync(c1, a, b, c1);
                }
                wmma::store_matrix_sync(acc + mt * 16 * LDF + p * 32,      c0, LDF,
                                        wmma::mem_row_major);
                wmma::store_matrix_sync(acc + mt * 16 * LDF + p * 32 + 16, c1, LDF,
                                        wmma::mem_row_major);
            }
            __syncthreads();

            for (int i = tid; i < 64 * 64; i += 512) {
                int r = i >> 6, k2 = i & 63;
                int k = k2 * 2;
                float x0 = acc[r * LDF + k]     + b2[ch * 128 + k];
                float x1 = acc[r * LDF + k + 1] + b2[ch * 128 + k + 1];
                ((half2*)(g_spn + (size_t)(n0 + r) * NOUT + ch * 128))[k2] =
                    __floats2half2_rn(x0, x1);
            }
            __syncthreads();
        }
    }
}

// ---------------------------------------------------------------------------
// Edge kernel: one warp per edge. fp16 gathers (g_spn, g_vh), fp32 table,
// v4 reductions straight into out_s and out_v (12 floats/lane = 3 float4s).
// ---------------------------------------------------------------------------
__global__ void edge_kernel(const float* __restrict__ pos,
                            const int* __restrict__ ei,
                            float* __restrict__ out) {
    const int gw   = (blockIdx.x * blockDim.x + threadIdx.x) >> 5;
    const int lane = threadIdx.x & 31;
    if (gw >= EE) return;

    const int src = ei[gw];
    const int dst = ei[EE + gw];

    float rx = pos[dst * 3 + 0] - pos[src * 3 + 0];
    float ry = pos[dst * 3 + 1] - pos[src * 3 + 1];
    float rz = pos[dst * 3 + 2] - pos[src * 3 + 2];
    float d  = fmaxf(sqrtf(rx * rx + ry * ry + rz * rz), 1e-6f);
    float iv = 1.0f / d;
    float u[3] = { rx * iv, ry * iv, rz * iv };

    float t = fminf(d, FCUT) * ((float)(NT - 1) / FCUT);
    int   i0 = (int)t;
    if (i0 > NT - 2) i0 = NT - 2;
    float f = t - (float)i0;

    const float4* t0 = (const float4*)(g_tab + (size_t)i0 * NOUT);
    const float4* t1 = t0 + 96;
    const uint2*  sp = (const uint2*)(g_spn + (size_t)src * NOUT);  // 4 halfs each
    const uint2*  vr = (const uint2*)(g_vh + (size_t)src * NOUT);

    // lane owns h = 4*lane .. 4*lane+3
    float4 t0a = t0[lane], t0b = t0[32 + lane], t0c = t0[64 + lane];
    float4 t1a = t1[lane], t1b = t1[32 + lane], t1c = t1[64 + lane];

    uint2 spa_u = sp[lane], spb_u = sp[32 + lane], spc_u = sp[64 + lane];
    uint2 v0u = vr[3 * lane + 0], v1u = vr[3 * lane + 1], v2u = vr[3 * lane + 2];

    float2 spa0 = __half22float2(*(half2*)&spa_u.x), spa1 = __half22float2(*(half2*)&spa_u.y);
    float2 spb0 = __half22float2(*(half2*)&spb_u.x), spb1 = __half22float2(*(half2*)&spb_u.y);
    float2 spc0 = __half22float2(*(half2*)&spc_u.x), spc1 = __half22float2(*(half2*)&spc_u.y);

    float2 va = __half22float2(*(half2*)&v0u.x), vb = __half22float2(*(half2*)&v0u.y);
    float2 vc = __half22float2(*(half2*)&v1u.x), vd = __half22float2(*(half2*)&v1u.y);
    float2 ve = __half22float2(*(half2*)&v2u.x), vf = __half22float2(*(half2*)&v2u.y);
    float vv[12] = { va.x, va.y, vb.x, vb.y, vc.x, vc.y,
                     vd.x, vd.y, ve.x, ve.y, vf.x, vf.y };

    float wS[4]  = { fmaf(f, t1a.x - t0a.x, t0a.x), fmaf(f, t1a.y - t0a.y, t0a.y),
                     fmaf(f, t1a.z - t0a.z, t0a.z), fmaf(f, t1a.w - t0a.w, t0a.w) };
    float w1v[4] = { fmaf(f, t1b.x - t0b.x, t0b.x), fmaf(f, t1b.y - t0b.y, t0b.y),
                     fmaf(f, t1b.z - t0b.z, t0b.z), fmaf(f, t1b.w - t0b.w, t0b.w) };
    float w2v[4] = { fmaf(f, t1c.x - t0c.x, t0c.x), fmaf(f, t1c.y - t0c.y, t0c.y),
                     fmaf(f, t1c.z - t0c.z, t0c.z), fmaf(f, t1c.w - t0c.w, t0c.w) };
    float spv[4] = { spa0.x, spa0.y, spa1.x, spa1.y };
    float sbv[4] = { spb0.x, spb0.y, spb1.x, spb1.y };
    float scv[4] = { spc0.x, spc0.y, spc1.x, spc1.y };
    float d1[4], d2[4];
    #pragma unroll
    for (int k = 0; k < 4; k++) {
        d1[k] = sbv[k] * w1v[k];
        d2[k] = scv[k] * w2v[k];
    }

    // scalar channel
    red_add_v4(out + (size_t)dst * HH + 4 * lane,
               spv[0] * wS[0], spv[1] * wS[1], spv[2] * wS[2], spv[3] * wS[3]);

    // vector channel: out_v[dst][4l..4l+3][0..2] = 12 consecutive floats
    float* pv = out + (size_t)NN * HH + (size_t)dst * NOUT + 12 * lane;
    red_add_v4(pv + 0,
               fmaf(d1[0], vv[0],  d2[0] * u[0]),
               fmaf(d1[0], vv[1],  d2[0] * u[1]),
               fmaf(d1[0], vv[2],  d2[0] * u[2]),
               fmaf(d1[1], vv[3],  d2[1] * u[0]));
    red_add_v4(pv + 4,
               fmaf(d1[1], vv[4],  d2[1] * u[1]),
               fmaf(d1[1], vv[5],  d2[1] * u[2]),
               fmaf(d1[2], vv[6],  d2[2] * u[0]),
               fmaf(d1[2], vv[7],  d2[2] * u[1]));
    red_add_v4(pv + 8,
               fmaf(d1[2], vv[8],  d2[2] * u[2]),
               fmaf(d1[3], vv[9],  d2[3] * u[0]),
               fmaf(d1[3], vv[10], d2[3] * u[1]),
               fmaf(d1[3], vv[11], d2[3] * u[2]));
}

// ---------------------------------------------------------------------------
extern "C" void kernel_launch(void* const* d_in, const int* in_sizes, int n_in,
                              void* d_out, int out_size) {
    const float* s      = (const float*)d_in[0];
    const float* v      = (const float*)d_in[1];
    const float* pos    = (const float*)d_in[2];
    const float* rbf_c  = (const float*)d_in[3];
    const float* rbf_w  = (const float*)d_in[4];
    const float* phi_w1 = (const float*)d_in[5];
    const float* phi_b1 = (const float*)d_in[6];
    const float* phi_w2 = (const float*)d_in[7];
    const float* phi_b2 = (const float*)d_in[8];
    const float* w_w1   = (const float*)d_in[9];
    const float* w_b1   = (const float*)d_in[10];
    const float* w_w2   = (const float*)d_in[11];
    const float* w_b2   = (const float*)d_in[12];
    const int*   ei     = (const int*)d_in[13];
    float* out = (float*)d_out;

    // 1) out_s = s ; out_v = v ; g_vh = half(v)
    {
        int n4 = NN * HH / 4 + NN * NOUT / 4;
        init_kernel<<<(n4 + 255) / 256, 256>>>(s, v, out);
    }
    // 2) distance->W table (fp32)
    build_tab_kernel<<<NT / 8, 128>>>(rbf_c, rbf_w, w_w1, w_b1, w_w2, w_b2);
    // 3) per-node scalar MLP (persistent fp16 WMMA, fp16 out + b2)
    {
        cudaFuncSetAttribute(node_mlp_fp16,
                             cudaFuncAttributeMaxDynamicSharedMemorySize, MLP_SMEM_BYTES);
        node_mlp_fp16<<<148, 512, MLP_SMEM_BYTES>>>(s, phi_w1, phi_b1, phi_w2, phi_b2);
    }
    // 4) edges (warp per edge, fp16 gathers + fp32 table, v4 reductions into out)
    {
        long long threads = (long long)EE * 32;
        edge_kernel<<<(int)((threads + 255) / 256), 256>>>(pos, ei, out);
    }
}

// round 17
// speedup vs baseline: 1.1464x; 1.1464x over previous
#include <cuda_runtime.h>
#include <cuda_fp16.h>
#include <math.h>
#include <mma.h>

using namespace nvcuda;

#define NN    50000
#define EE    400000
#define HH    128
#define NRBFN 20
#define NOUT  384          // 3*H
#define FCUT  8.0f
#define NT    4096         // distance table resolution

#define NROWPAD 50048      // NN rounded up to 64
#define NTILES  782        // NROWPAD / 64
#define LDH     136        // padded half row (128+8): <=2-way bank conflicts
#define LDF     132        // padded float row

// Scratch (device globals: allocation-free rule)
__device__ __align__(16) half g_spn[NROWPAD * NOUT]; // fp16 sp+b2, 38.4 MB
__device__ __align__(16) half g_vh[NN * NOUT];       // fp16 copy of v, 38.4 MB
__device__ float g_tab[NT * NOUT];                   // fp32 W(d) table, 6.3 MB (L2)

__device__ __forceinline__ float silu_f(float x) {
    return x / (1.0f + __expf(-x));
}

__device__ __forceinline__ void red_add_v4(float* p, float a, float b, float c, float d) {
    asm volatile("red.global.add.v4.f32 [%0], {%1,%2,%3,%4};"
                 :: "l"(p), "f"(a), "f"(b), "f"(c), "f"(d) : "memory");
}

// ---------------------------------------------------------------------------
// Kernel 0: out_s = s ; out_v = v ; g_vh = fp16(v)
// ---------------------------------------------------------------------------
__global__ void init_kernel(const float* __restrict__ s,
                            const float* __restrict__ v,
                            float* __restrict__ out) {
    int i = blockIdx.x * blockDim.x + threadIdx.x;       // float4 index
    const int nS4 = NN * HH / 4;          // 1.6M  : out_s = s
    const int nV4 = NN * NOUT / 4;        // 4.8M  : out_v = v, g_vh = half(v)
    if (i < nS4) {
        ((float4*)out)[i] = ((const float4*)s)[i];
    } else if (i < nS4 + nV4) {
        int j = i - nS4;
        float4 x = ((const float4*)v)[j];
        ((float4*)(out + (size_t)NN * HH))[j] = x;
        half2 h0 = __floats2half2_rn(x.x, x.y);
        half2 h1 = __floats2half2_rn(x.z, x.w);
        unsigned u0 = *reinterpret_cast<unsigned*>(&h0);
        unsigned u1 = *reinterpret_cast<unsigned*>(&h1);
        ((uint2*)g_vh)[j] = make_uint2(u0, u1);
    }
}

// ---------------------------------------------------------------------------
// W(d) table (fp32). 8 rows per block, 128 threads. float4 W2 reads.
// ---------------------------------------------------------------------------
__global__ void build_tab_kernel(const float* __restrict__ rbf_c,
                                 const float* __restrict__ rbf_w,
                                 const float* __restrict__ w1,   // [128,20]
                                 const float* __restrict__ b1,   // [128]
                                 const float* __restrict__ w2,   // [384,128]
                                 const float* __restrict__ b2) { // [384]
    __shared__ float feat_sm[8][NRBFN];
    __shared__ float g_sm[8][HH];
    const int tid  = threadIdx.x;        // 128
    const int row0 = blockIdx.x * 8;

    for (int idx = tid; idx < 8 * NRBFN; idx += 128) {
        int r = idx / NRBFN, i = idx % NRBFN;
        float d   = (row0 + r) * (FCUT / (float)(NT - 1));
        float x   = d / FCUT;
        float env = (x < 1.0f) ? 0.5f * (__cosf(3.14159265358979f * x) + 1.0f) : 0.0f;
        float df  = d - rbf_c[i];
        feat_sm[r][i] = __expf(-fabsf(rbf_w[i]) * df * df) * env;
    }
    __syncthreads();

    float wrow[NRBFN];
    #pragma unroll
    for (int i = 0; i < NRBFN; i++) wrow[i] = w1[tid * NRBFN + i];
    float bb = b1[tid];
    #pragma unroll
    for (int r = 0; r < 8; r++) {
        float a = bb;
        #pragma unroll
        for (int i = 0; i < NRBFN; i++) a += feat_sm[r][i] * wrow[i];
        g_sm[r][tid] = silu_f(a);
    }
    __syncthreads();

    float a0[8], a1[8], a2[8];
    #pragma unroll
    for (int r = 0; r < 8; r++) { a0[r] = 0.f; a1[r] = 0.f; a2[r] = 0.f; }
    const float4* w2r0 = (const float4*)(w2 + (tid)       * HH);
    const float4* w2r1 = (const float4*)(w2 + (tid + 128) * HH);
    const float4* w2r2 = (const float4*)(w2 + (tid + 256) * HH);
    for (int k4 = 0; k4 < HH / 4; k4++) {
        float4 x0 = w2r0[k4], x1 = w2r1[k4], x2 = w2r2[k4];
        #pragma unroll
        for (int r = 0; r < 8; r++) {
            const float* gr = &g_sm[r][k4 * 4];
            float h0 = gr[0], h1 = gr[1], h2 = gr[2], h3 = gr[3];
            a0[r] += h0 * x0.x + h1 * x0.y + h2 * x0.z + h3 * x0.w;
            a1[r] += h0 * x1.x + h1 * x1.y + h2 * x1.z + h3 * x1.w;
            a2[r] += h0 * x2.x + h1 * x2.y + h2 * x2.z + h3 * x2.w;
        }
    }
    float c0 = b2[tid], c1 = b2[tid + 128], c2 = b2[tid + 256];
    #pragma unroll
    for (int r = 0; r < 8; r++) {
        float* o = g_tab + (size_t)(row0 + r) * NOUT;
        o[tid]       = a0[r] + c0;
        o[tid + 128] = a1[r] + c1;
        o[tid + 256] = a2[r] + c2;
    }
}

// ---------------------------------------------------------------------------
// Node scalar MLP: persistent fp16 WMMA GEMM, fp16 output with b2 folded in.
// grid=148, 512 threads (16 warps). Weights staged ONCE in padded smem.
// 2-n-tile register blocking per warp (shared A fragment).
// ---------------------------------------------------------------------------
#define MLP_SMEM_BYTES (128*LDH*2 + 384*LDH*2 + 64*LDH*2 + 64*LDH*2 + 64*LDF*4)

__global__ void __launch_bounds__(512, 1)
node_mlp_fp16(const float* __restrict__ s,
              const float* __restrict__ w1,   // [128,128]
              const float* __restrict__ b1,
              const float* __restrict__ w2,   // [384,128]
              const float* __restrict__ b2) { // [384]
    extern __shared__ char smx[];
    half*  w1_h = (half*)smx;                    // 128*136
    half*  w2_h = w1_h + 128 * LDH;              // 384*136
    half*  s_h  = w2_h + 384 * LDH;              // 64*136
    half*  h_h  = s_h  + 64 * LDH;               // 64*136
    float* acc  = (float*)(h_h + 64 * LDH);      // 64*132

    const int tid  = threadIdx.x;                // 512
    const int warp = tid >> 5;                   // 16 warps
    const int mt   = warp >> 2;                  // m-tile 0..3
    const int p    = warp & 3;                   // n-pair 0..3 (tiles 2p, 2p+1)

    // ---- stage weights once ----
    for (int q = tid; q < 128 * 32; q += 512) {
        int r = q >> 5, c4 = q & 31;
        float4 x = ((const float4*)w1)[q];
        half2* d = (half2*)(w1_h + r * LDH + c4 * 4);
        d[0] = __floats2half2_rn(x.x, x.y);
        d[1] = __floats2half2_rn(x.z, x.w);
    }
    for (int q = tid; q < 384 * 32; q += 512) {
        int r = q >> 5, c4 = q & 31;
        float4 x = ((const float4*)w2)[q];
        half2* d = (half2*)(w2_h + r * LDH + c4 * 4);
        d[0] = __floats2half2_rn(x.x, x.y);
        d[1] = __floats2half2_rn(x.z, x.w);
    }
    __syncthreads();

    for (int t = blockIdx.x; t < NTILES; t += gridDim.x) {
        const int n0 = t * 64;

        for (int q = tid; q < 64 * 32; q += 512) {
            int r  = q >> 5, c4 = q & 31;
            int gr = n0 + r; if (gr >= NN) gr = NN - 1;
            float4 x = ((const float4*)s)[gr * 32 + c4];
            half2* d = (half2*)(s_h + r * LDH + c4 * 4);
            d[0] = __floats2half2_rn(x.x, x.y);
            d[1] = __floats2half2_rn(x.z, x.w);
        }
        __syncthreads();

        // ---- layer 1 ----
        {
            wmma::fragment<wmma::accumulator, 16, 16, 16, float> c0, c1;
            wmma::fill_fragment(c0, 0.0f);
            wmma::fill_fragment(c1, 0.0f);
            for (int k = 0; k < HH; k += 16) {
                wmma::fragment<wmma::matrix_a, 16, 16, 16, half, wmma::row_major> a;
                wmma::load_matrix_sync(a, s_h + mt * 16 * LDH + k, LDH);
                wmma::fragment<wmma::matrix_b, 16, 16, 16, half, wmma::col_major> b;
                wmma::load_matrix_sync(b, w1_h + (p * 32) * LDH + k, LDH);
                wmma::mma_sync(c0, a, b, c0);
                wmma::load_matrix_sync(b, w1_h + (p * 32 + 16) * LDH + k, LDH);
                wmma::mma_sync(c1, a, b, c1);
            }
            wmma::store_matrix_sync(acc + mt * 16 * LDF + p * 32,      c0, LDF,
                                    wmma::mem_row_major);
            wmma::store_matrix_sync(acc + mt * 16 * LDF + p * 32 + 16, c1, LDF,
                                    wmma::mem_row_major);
        }
        __syncthreads();

        for (int i = tid; i < 64 * 128; i += 512) {
            int r = i >> 7, k = i & 127;
            h_h[r * LDH + k] = __float2half(silu_f(acc[r * LDF + k] + b1[k]));
        }
        __syncthreads();

        // ---- layer 2: 3 chunks of 128 cols ----
        #pragma unroll 1
        for (int ch = 0; ch < 3; ch++) {
            {
                wmma::fragment<wmma::accumulator, 16, 16, 16, float> c0, c1;
                wmma::fill_fragment(c0, 0.0f);
                wmma::fill_fragment(c1, 0.0f);
                for (int k = 0; k < HH; k += 16) {
                    wmma::fragment<wmma::matrix_a, 16, 16, 16, half, wmma::row_major> a;
                    wmma::load_matrix_sync(a, h_h + mt * 16 * LDH + k, LDH);
                    wmma::fragment<wmma::matrix_b, 16, 16, 16, half, wmma::col_major> b;
                    wmma::load_matrix_sync(b, w2_h + (ch * 128 + p * 32) * LDH + k, LDH);
                    wmma::mma_sync(c0, a, b, c0);
                    wmma::load_matrix_sync(b, w2_h + (ch * 128 + p * 32 + 16) * LDH + k, LDH);
                    wmma::mma_sync(c1, a, b, c1);
                }
                wmma::store_matrix_sync(acc + mt * 16 * LDF + p * 32,      c0, LDF,
                                        wmma::mem_row_major);
                wmma::store_matrix_sync(acc + mt * 16 * LDF + p * 32 + 16, c1, LDF,
                                        wmma::mem_row_major);
            }
            __syncthreads();

            for (int i = tid; i < 64 * 64; i += 512) {
                int r = i >> 6, k2 = i & 63;
                int k = k2 * 2;
                float x0 = acc[r * LDF + k]     + b2[ch * 128 + k];
                float x1 = acc[r * LDF + k + 1] + b2[ch * 128 + k + 1];
                ((half2*)(g_spn + (size_t)(n0 + r) * NOUT + ch * 128))[k2] =
                    __floats2half2_rn(x0, x1);
            }
            __syncthreads();
        }
    }
}

// ---------------------------------------------------------------------------
// Edge kernel: one warp per edge. fp16 gathers (g_spn, g_vh), fp32 table.
// Vector messages transposed through smem per-warp so each red.v4 is a
// warp-contiguous 512B write (coalesced reds into out_v directly).
// ---------------------------------------------------------------------------
__global__ void edge_kernel(const float* __restrict__ pos,
                            const int* __restrict__ ei,
                            float* __restrict__ out) {
    __shared__ __align__(16) float xch[8][NOUT];   // 12 KB: per-warp exchange
    const int gw   = (blockIdx.x * blockDim.x + threadIdx.x) >> 5;
    const int lane = threadIdx.x & 31;
    const int wl   = (threadIdx.x >> 5) & 7;
    if (gw >= EE) return;

    const int src = ei[gw];
    const int dst = ei[EE + gw];

    float rx = pos[dst * 3 + 0] - pos[src * 3 + 0];
    float ry = pos[dst * 3 + 1] - pos[src * 3 + 1];
    float rz = pos[dst * 3 + 2] - pos[src * 3 + 2];
    float d  = fmaxf(sqrtf(rx * rx + ry * ry + rz * rz), 1e-6f);
    float iv = 1.0f / d;
    float u[3] = { rx * iv, ry * iv, rz * iv };

    float t = fminf(d, FCUT) * ((float)(NT - 1) / FCUT);
    int   i0 = (int)t;
    if (i0 > NT - 2) i0 = NT - 2;
    float f = t - (float)i0;

    const float4* t0 = (const float4*)(g_tab + (size_t)i0 * NOUT);
    const float4* t1 = t0 + 96;
    const uint2*  sp = (const uint2*)(g_spn + (size_t)src * NOUT);
    const uint2*  vr = (const uint2*)(g_vh + (size_t)src * NOUT);

    // lane owns h = 4*lane .. 4*lane+3
    float4 t0a = t0[lane], t0b = t0[32 + lane], t0c = t0[64 + lane];
    float4 t1a = t1[lane], t1b = t1[32 + lane], t1c = t1[64 + lane];

    uint2 spa_u = sp[lane], spb_u = sp[32 + lane], spc_u = sp[64 + lane];
    uint2 v0u = vr[3 * lane + 0], v1u = vr[3 * lane + 1], v2u = vr[3 * lane + 2];

    float2 spa0 = __half22float2(*(half2*)&spa_u.x), spa1 = __half22float2(*(half2*)&spa_u.y);
    float2 spb0 = __half22float2(*(half2*)&spb_u.x), spb1 = __half22float2(*(half2*)&spb_u.y);
    float2 spc0 = __half22float2(*(half2*)&spc_u.x), spc1 = __half22float2(*(half2*)&spc_u.y);

    float2 va = __half22float2(*(half2*)&v0u.x), vb = __half22float2(*(half2*)&v0u.y);
    float2 vc = __half22float2(*(half2*)&v1u.x), vd = __half22float2(*(half2*)&v1u.y);
    float2 ve = __half22float2(*(half2*)&v2u.x), vf = __half22float2(*(half2*)&v2u.y);
    float vv[12] = { va.x, va.y, vb.x, vb.y, vc.x, vc.y,
                     vd.x, vd.y, ve.x, ve.y, vf.x, vf.y };

    float wS[4]  = { fmaf(f, t1a.x - t0a.x, t0a.x), fmaf(f, t1a.y - t0a.y, t0a.y),
                     fmaf(f, t1a.z - t0a.z, t0a.z), fmaf(f, t1a.w - t0a.w, t0a.w) };
    float w1v[4] = { fmaf(f, t1b.x - t0b.x, t0b.x), fmaf(f, t1b.y - t0b.y, t0b.y),
                     fmaf(f, t1b.z - t0b.z, t0b.z), fmaf(f, t1b.w - t0b.w, t0b.w) };
    float w2v[4] = { fmaf(f, t1c.x - t0c.x, t0c.x), fmaf(f, t1c.y - t0c.y, t0c.y),
                     fmaf(f, t1c.z - t0c.z, t0c.z), fmaf(f, t1c.w - t0c.w, t0c.w) };
    float spv[4] = { spa0.x, spa0.y, spa1.x, spa1.y };
    float sbv[4] = { spb0.x, spb0.y, spb1.x, spb1.y };
    float scv[4] = { spc0.x, spc0.y, spc1.x, spc1.y };
    float d1[4], d2[4];
    #pragma unroll
    for (int k = 0; k < 4; k++) {
        d1[k] = sbv[k] * w1v[k];
        d2[k] = scv[k] * w2v[k];
    }

    // scalar channel (already warp-contiguous)
    red_add_v4(out + (size_t)dst * HH + 4 * lane,
               spv[0] * wS[0], spv[1] * wS[1], spv[2] * wS[2], spv[3] * wS[3]);

    // vector messages: 12 floats per lane -> smem, then coalesced red.v4
    float* xw = xch[wl];
    float4* xw4 = (float4*)(xw + 12 * lane);
    xw4[0] = make_float4(fmaf(d1[0], vv[0],  d2[0] * u[0]),
                         fmaf(d1[0], vv[1],  d2[0] * u[1]),
                         fmaf(d1[0], vv[2],  d2[0] * u[2]),
                         fmaf(d1[1], vv[3],  d2[1] * u[0]));
    xw4[1] = make_float4(fmaf(d1[1], vv[4],  d2[1] * u[1]),
                         fmaf(d1[1], vv[5],  d2[1] * u[2]),
                         fmaf(d1[2], vv[6],  d2[2] * u[0]),
                         fmaf(d1[2], vv[7],  d2[2] * u[1]));
    xw4[2] = make_float4(fmaf(d1[2], vv[8],  d2[2] * u[2]),
                         fmaf(d1[3], vv[9],  d2[3] * u[0]),
                         fmaf(d1[3], vv[10], d2[3] * u[1]),
                         fmaf(d1[3], vv[11], d2[3] * u[2]));
    __syncwarp();

    float* pv = out + (size_t)NN * HH + (size_t)dst * NOUT;
    #pragma unroll
    for (int j = 0; j < 3; j++) {
        int q = lane + 32 * j;                 // float4 index within row
        float4 x = ((const float4*)xw)[q];
        red_add_v4(pv + 4 * q, x.x, x.y, x.z, x.w);
    }
}

// ---------------------------------------------------------------------------
extern "C" void kernel_launch(void* const* d_in, const int* in_sizes, int n_in,
                              void* d_out, int out_size) {
    const float* s      = (const float*)d_in[0];
    const float* v      = (const float*)d_in[1];
    const float* pos    = (const float*)d_in[2];
    const float* rbf_c  = (const float*)d_in[3];
    const float* rbf_w  = (const float*)d_in[4];
    const float* phi_w1 = (const float*)d_in[5];
    const float* phi_b1 = (const float*)d_in[6];
    const float* phi_w2 = (const float*)d_in[7];
    const float* phi_b2 = (const float*)d_in[8];
    const float* w_w1   = (const float*)d_in[9];
    const float* w_b1   = (const float*)d_in[10];
    const float* w_w2   = (const float*)d_in[11];
    const float* w_b2   = (const float*)d_in[12];
    const int*   ei     = (const int*)d_in[13];
    float* out = (float*)d_out;

    // 1) out_s = s ; out_v = v ; g_vh = half(v)
    {
        int n4 = NN * HH / 4 + NN * NOUT / 4;
        init_kernel<<<(n4 + 255) / 256, 256>>>(s, v, out);
    }
    // 2) distance->W table (fp32)
    build_tab_kernel<<<NT / 8, 128>>>(rbf_c, rbf_w, w_w1, w_b1, w_w2, w_b2);
    // 3) per-node scalar MLP (persistent fp16 WMMA, fp16 out + b2)
    {
        cudaFuncSetAttribute(node_mlp_fp16,
                             cudaFuncAttributeMaxDynamicSharedMemorySize, MLP_SMEM_BYTES);
        node_mlp_fp16<<<148, 512, MLP_SMEM_BYTES>>>(s, phi_w1, phi_b1, phi_w2, phi_b2);
    }
    // 4) edges (warp per edge, fp16 gathers, smem-transposed coalesced reds)
    {
        long long threads = (long long)EE * 32;
        edge_kernel<<<(int)((threads + 255) / 256), 256>>>(pos, ei, out);
    }
}